// round 3
// baseline (speedup 1.0000x reference)
#include <cuda_runtime.h>
#include <math.h>

// Problem dims (fixed by dataset)
#define BB 64
#define TT 2048
#define DD 256

#define ROWS  32          // rows per block in scores kernel
#define PAIRS (ROWS / 2)  // packed f32x2 row pairs
#define CHUNK 128         // T-chunk per block in output kernel

// Scratch (allocation-free rule: __device__ globals)
__device__ float g_aun[BB * TT];   // unnormalized a = exp(s) * mask
__device__ float g_denom[BB];      // per-batch sum + EPS

// ---------------------------------------------------------------------------
// packed fp32x2 helpers (Blackwell dual-rate FP32 path; only reachable via PTX)
// ---------------------------------------------------------------------------
__device__ __forceinline__ unsigned long long pk2(float lo, float hi) {
    unsigned long long r;
    asm("mov.b64 %0, {%1, %2};" : "=l"(r) : "f"(lo), "f"(hi));
    return r;
}
__device__ __forceinline__ void unpk2(unsigned long long v, float& lo, float& hi) {
    asm("mov.b64 {%0, %1}, %2;" : "=f"(lo), "=f"(hi) : "l"(v));
}
__device__ __forceinline__ unsigned long long ffma2(unsigned long long a,
                                                    unsigned long long b,
                                                    unsigned long long c) {
    unsigned long long d;
    asm("fma.rn.f32x2 %0, %1, %2, %3;" : "=l"(d) : "l"(a), "l"(b), "l"(c));
    return d;
}

// ---------------------------------------------------------------------------
// K1: scores.  For each row (b,t): y_e = sum_d x_d * W[d,e]; then
// s = sum_e uw_e * tanh(y_e + b_e);  a_un = exp(s) * mask.
// Block = 32 rows x 256 cols. Thread e owns column e; rows broadcast from
// SMEM as packed pairs so the inner loop is pure FFMA2.
// ---------------------------------------------------------------------------
__global__ void __launch_bounds__(256) scores_kernel(
    const float* __restrict__ x, const float* __restrict__ W,
    const float* __restrict__ bias, const float* __restrict__ uw,
    const int* __restrict__ mask)
{
    __shared__ unsigned long long xs[PAIRS][DD];  // 16*256*8 = 32 KB
    __shared__ float red[8][ROWS];                // [warp][row] partials

    const int e = threadIdx.x;
    const long long row0 = (long long)blockIdx.x * ROWS;

    // Load 32 rows of x, packed into row-pairs (coalesced per row).
#pragma unroll
    for (int p = 0; p < PAIRS; p++) {
        float a0 = x[(row0 + 2 * p) * DD + e];
        float a1 = x[(row0 + 2 * p + 1) * DD + e];
        xs[p][e] = pk2(a0, a1);
    }
    __syncthreads();

    unsigned long long acc[PAIRS];
#pragma unroll
    for (int p = 0; p < PAIRS; p++) acc[p] = 0ull;  // (0.0f, 0.0f)

    const float* __restrict__ wcol = W + e;  // column e, stride DD
#pragma unroll 4
    for (int d = 0; d < DD; d++) {
        float w = __ldg(wcol + (size_t)d * DD);   // coalesced across warp; L2-hot
        unsigned long long w2 = pk2(w, w);
#pragma unroll
        for (int p = 0; p < PAIRS; p++) {
            acc[p] = ffma2(xs[p][d], w2, acc[p]); // 2 FMAs per instr
        }
    }

    const float be = bias[e];
    const float ue = uw[e];
    const int warp = e >> 5, lane = e & 31;

    // Per-row reduction over the 256 columns.
#pragma unroll
    for (int p = 0; p < PAIRS; p++) {
        float y0, y1;
        unpk2(acc[p], y0, y1);
        float v0 = ue * tanhf(y0 + be);
        float v1 = ue * tanhf(y1 + be);
#pragma unroll
        for (int off = 16; off > 0; off >>= 1) {
            v0 += __shfl_down_sync(0xFFFFFFFFu, v0, off);
            v1 += __shfl_down_sync(0xFFFFFFFFu, v1, off);
        }
        if (lane == 0) {
            red[warp][2 * p]     = v0;
            red[warp][2 * p + 1] = v1;
        }
    }
    __syncthreads();

    if (e < ROWS) {
        float s = 0.f;
#pragma unroll
        for (int w = 0; w < 8; w++) s += red[w][e];
        long long row = row0 + e;
        float m = (float)mask[row];
        g_aun[row] = expf(s) * m;   // plain exp, matching reference (no max-sub)
    }
}

// ---------------------------------------------------------------------------
// K2: per-batch denominator (sum over T) + EPS.
// ---------------------------------------------------------------------------
__global__ void __launch_bounds__(256) denom_kernel()
{
    __shared__ float red[8];
    const int b = blockIdx.x;
    float s = 0.f;
    for (int t = threadIdx.x; t < TT; t += 256)
        s += g_aun[(size_t)b * TT + t];
#pragma unroll
    for (int off = 16; off > 0; off >>= 1)
        s += __shfl_down_sync(0xFFFFFFFFu, s, off);
    const int warp = threadIdx.x >> 5, lane = threadIdx.x & 31;
    if (lane == 0) red[warp] = s;
    __syncthreads();
    if (threadIdx.x == 0) {
        float tot = 0.f;
#pragma unroll
        for (int w = 0; w < 8; w++) tot += red[w];
        g_denom[b] = tot + 1e-7f;
    }
}

// ---------------------------------------------------------------------------
// K3a: zero output (d_out is poisoned by harness).
// ---------------------------------------------------------------------------
__global__ void zero_kernel(float* __restrict__ out)
{
    out[blockIdx.x * blockDim.x + threadIdx.x] = 0.f;
}

// ---------------------------------------------------------------------------
// K3: out[b,e] = sum_t x[b,t,e] * a_un[b,t] / denom[b].
// Grid (T/CHUNK, B); partials via atomicAdd (16 per address — negligible).
// ---------------------------------------------------------------------------
__global__ void __launch_bounds__(256) out_kernel(
    const float* __restrict__ x, float* __restrict__ out)
{
    const int b = blockIdx.y;
    const int e = threadIdx.x;
    const int t0 = blockIdx.x * CHUNK;
    const float invd = 1.0f / g_denom[b];

    float acc = 0.f;
    const float* __restrict__ xp = x + ((size_t)b * TT + t0) * DD + e;
    const float* __restrict__ ap = g_aun + (size_t)b * TT + t0;
#pragma unroll 4
    for (int t = 0; t < CHUNK; t++) {
        acc += xp[(size_t)t * DD] * ap[t];
    }
    atomicAdd(&out[b * DD + e], acc * invd);
}

// ---------------------------------------------------------------------------
extern "C" void kernel_launch(void* const* d_in, const int* in_sizes, int n_in,
                              void* d_out, int out_size)
{
    const float* x    = (const float*)d_in[0];
    const float* W    = (const float*)d_in[1];
    const float* bias = (const float*)d_in[2];
    const float* uw   = (const float*)d_in[3];
    const int*   mask = (const int*)d_in[4];
    float* out = (float*)d_out;

    scores_kernel<<<(BB * TT) / ROWS, 256>>>(x, W, bias, uw, mask);
    denom_kernel<<<BB, 256>>>();
    zero_kernel<<<(BB * DD) / 256, 256>>>(out);
    out_kernel<<<dim3(TT / CHUNK, BB), 256>>>(x, out);
}

// round 6
// speedup vs baseline: 2.1809x; 2.1809x over previous
#include <cuda_runtime.h>
#include <cuda_bf16.h>
#include <math.h>
#include <stdint.h>

// Problem dims (fixed by dataset)
#define BB 64
#define TT 2048
#define DD 256

// scores kernel tiling (mma.sync path: tcgen05 not reachable — harness lowers
// through compute_103 virtual arch, which rejects all 'a'-gated instructions)
#define M_TILE 128        // rows per CTA
#define KC 64             // K chunk (bf16 row = 128B swizzle atom)
#define NCH 4             // DD / KC
#define THREADS_SC 256    // 8 warps

// dynamic smem layout (bytes; tiles 1024-aligned for the XOR swizzle)
#define OFF_AH   0                  // 128 x 64 bf16 = 16 KB
#define OFF_AL   16384
#define OFF_BH   32768              // 256 x 64 bf16 = 32 KB
#define OFF_BL   65536
#define OFF_RED  98304              // 128 x 2 fp32
#define OFF_UW   99328
#define OFF_BIAS 100352
#define SMEM_SC  101376

// ---------------------------------------------------------------------------
// device scratch (allocation-free rule: __device__ globals)
// ---------------------------------------------------------------------------
__device__ float g_aun[BB * TT];                 // exp(s) * mask
__device__ float g_denom[BB];                    // per-batch sum + EPS
__device__ __nv_bfloat16 g_Whi[NCH * DD * KC];   // W^T hi, pre-swizzled chunks
__device__ __nv_bfloat16 g_Wlo[NCH * DD * KC];   // W^T lo, pre-swizzled chunks

// ---------------------------------------------------------------------------
// helpers
// ---------------------------------------------------------------------------
__device__ __forceinline__ uint32_t smem_u32(const void* p) {
    uint32_t a;
    asm("{ .reg .u64 t; cvta.to.shared.u64 t, %1; cvt.u32.u64 %0, t; }"
        : "=r"(a) : "l"(p));
    return a;
}

#define SWZ(off) ((off) ^ (((off) >> 3) & 0x70))

__device__ __forceinline__ uint32_t pkbf2(float a, float b) {
    __nv_bfloat162 h = __floats2bfloat162_rn(a, b);   // .x (low) = a
    return *reinterpret_cast<uint32_t*>(&h);
}

__device__ __forceinline__ void ldsm_x4(uint32_t* q, uint32_t addr) {
    asm volatile("ldmatrix.sync.aligned.m8n8.x4.shared.b16 {%0,%1,%2,%3}, [%4];"
                 : "=r"(q[0]), "=r"(q[1]), "=r"(q[2]), "=r"(q[3]) : "r"(addr));
}

__device__ __forceinline__ void mma_16816(float* d, const uint32_t* a,
                                          uint32_t b0, uint32_t b1) {
    asm volatile(
        "mma.sync.aligned.m16n8k16.row.col.f32.bf16.bf16.f32 "
        "{%0,%1,%2,%3}, {%4,%5,%6,%7}, {%8,%9}, {%0,%1,%2,%3};"
        : "+f"(d[0]), "+f"(d[1]), "+f"(d[2]), "+f"(d[3])
        : "r"(a[0]), "r"(a[1]), "r"(a[2]), "r"(a[3]), "r"(b0), "r"(b1));
}

// ---------------------------------------------------------------------------
// prep: W^T split into bf16 hi/lo, stored as pre-swizzled 32KB chunk images
// (chunk kc holds cols d = kc*64..kc*64+63 for all 256 e-rows, K-contiguous)
// ---------------------------------------------------------------------------
__global__ void __launch_bounds__(256) prep_w_kernel(const float* __restrict__ W)
{
    const int d = blockIdx.x;    // K index
    const int e = threadIdx.x;   // N index
    float w = W[d * DD + e];
    __nv_bfloat16 h = __float2bfloat16(w);
    __nv_bfloat16 l = __float2bfloat16(w - __bfloat162float(h));
    const int kc = d >> 6, dl = d & 63;
    uint32_t sw = SWZ((uint32_t)(e * 128 + dl * 2));
    g_Whi[kc * (DD * KC) + (sw >> 1)] = h;
    g_Wlo[kc * (DD * KC) + (sw >> 1)] = l;
}

// ---------------------------------------------------------------------------
// K1: scores via mma.sync bf16x3.  y[128,256] = x @ W (fp32 accum in regs),
// then per-row s = sum_e uw_e * tanh(y+b_e);  g_aun = exp(s)*mask.
// Warp w: rows [(w>>1)*32, +32), cols [(w&1)*128, +128).
// ---------------------------------------------------------------------------
__global__ void __launch_bounds__(THREADS_SC, 1) scores_mma_kernel(
    const float* __restrict__ x, const float* __restrict__ bias,
    const float* __restrict__ uw, const int* __restrict__ mask)
{
    extern __shared__ char smem[];
    const uint32_t sb = smem_u32(smem);
    const int tid  = threadIdx.x;
    const int wid  = tid >> 5;
    const int lane = tid & 31;

    const int mbase = (wid >> 1) * 32;       // warp's row base
    const int ncol0 = (wid & 1) * 128;       // warp's col base

    float* red_s  = (float*)(smem + OFF_RED);
    float* uw_s   = (float*)(smem + OFF_UW);
    float* bias_s = (float*)(smem + OFF_BIAS);
    for (int i = tid; i < DD; i += THREADS_SC) { uw_s[i] = uw[i]; bias_s[i] = bias[i]; }

    const long long row0 = (long long)blockIdx.x * M_TILE;
    const float4* __restrict__ x4 = (const float4*)(x + row0 * DD);

    float acc[2][16][4];
#pragma unroll
    for (int mt = 0; mt < 2; mt++)
#pragma unroll
        for (int j = 0; j < 16; j++)
#pragma unroll
            for (int v = 0; v < 4; v++) acc[mt][j][v] = 0.f;

    // per-lane ldmatrix address components (x4 lane-group layout)
    const int r_a = (lane & 7) + ((lane >> 3) & 1) * 8;   // A: row within m16
    const int k_a = (lane >> 4) * 8;                      // A: k offset
    const int r_b = (lane & 7) + ((lane >> 4) & 1) * 8;   // B: n within pair
    const int k_b = ((lane >> 3) & 1) * 8;                // B: k offset

    for (int kc = 0; kc < NCH; kc++) {
        // --- stage W chunk (pre-swizzled: straight linear copy, L2-hot) ---
        const uint4* __restrict__ wh = (const uint4*)(g_Whi + kc * (DD * KC));
        const uint4* __restrict__ wl = (const uint4*)(g_Wlo + kc * (DD * KC));
        uint4* sbh = (uint4*)(smem + OFF_BH);
        uint4* sbl = (uint4*)(smem + OFF_BL);
#pragma unroll 2
        for (int i = tid; i < 2048; i += THREADS_SC) { sbh[i] = wh[i]; sbl[i] = wl[i]; }

        // --- load + split x chunk into swizzled bf16 hi/lo tiles ---
#pragma unroll 2
        for (int i = tid; i < 2048; i += THREADS_SC) {
            const int r = i >> 4, seg = i & 15;
            float4 v = x4[r * (DD / 4) + kc * (KC / 4) + seg];
            float hx = __bfloat162float(__float2bfloat16(v.x));
            float hy = __bfloat162float(__float2bfloat16(v.y));
            float hz = __bfloat162float(__float2bfloat16(v.z));
            float hw = __bfloat162float(__float2bfloat16(v.w));
            uint32_t h01 = pkbf2(v.x, v.y), h23 = pkbf2(v.z, v.w);
            uint32_t l01 = pkbf2(v.x - hx, v.y - hy), l23 = pkbf2(v.z - hz, v.w - hw);
            uint32_t sw = SWZ((uint32_t)(r * 128 + seg * 8));
            *(uint2*)(smem + OFF_AH + sw) = make_uint2(h01, h23);
            *(uint2*)(smem + OFF_AL + sw) = make_uint2(l01, l23);
        }
        __syncthreads();

        // --- compute: 4 K16 steps x (2 m-tiles x 16 n-tiles) x 3 products ---
        for (int ks = 0; ks < 4; ks++) {
            const int kk = ks * 16;
            uint32_t ah[2][4], al[2][4];
#pragma unroll
            for (int mt = 0; mt < 2; mt++) {
                uint32_t ao = SWZ((uint32_t)((mbase + mt * 16 + r_a) * 128 + (kk + k_a) * 2));
                ldsm_x4(ah[mt], sb + OFF_AH + ao);
                ldsm_x4(al[mt], sb + OFF_AL + ao);
            }
#pragma unroll
            for (int p = 0; p < 8; p++) {
                uint32_t bo = SWZ((uint32_t)((ncol0 + p * 16 + r_b) * 128 + (kk + k_b) * 2));
                uint32_t bh[4], bl[4];
                ldsm_x4(bh, sb + OFF_BH + bo);
                ldsm_x4(bl, sb + OFF_BL + bo);
#pragma unroll
                for (int mt = 0; mt < 2; mt++) {
                    mma_16816(acc[mt][2 * p],     ah[mt], bh[0], bh[1]);
                    mma_16816(acc[mt][2 * p + 1], ah[mt], bh[2], bh[3]);
                    mma_16816(acc[mt][2 * p],     al[mt], bh[0], bh[1]);
                    mma_16816(acc[mt][2 * p + 1], al[mt], bh[2], bh[3]);
                    mma_16816(acc[mt][2 * p],     ah[mt], bl[0], bl[1]);
                    mma_16816(acc[mt][2 * p + 1], ah[mt], bl[2], bl[3]);
                }
            }
        }
        __syncthreads();   // tiles reused next chunk
    }

    // --- epilogue: tanh + uw-dot on fragments ---
    // thread cells: rows R = mbase + mt*16 + (lane>>2) (+8), cols C = ncol0 + j*8 + (lane&3)*2 (+1)
    float part[4] = {0.f, 0.f, 0.f, 0.f};
#pragma unroll
    for (int mt = 0; mt < 2; mt++) {
#pragma unroll
        for (int j = 0; j < 16; j++) {
            const int C = ncol0 + j * 8 + (lane & 3) * 2;
            const float u0 = uw_s[C], u1 = uw_s[C + 1];
            const float b0 = bias_s[C], b1 = bias_s[C + 1];
#pragma unroll
            for (int h = 0; h < 2; h++) {   // h=0: row R, h=1: row R+8
                float y0 = acc[mt][j][2 * h]     + b0;
                float y1 = acc[mt][j][2 * h + 1] + b1;
                // tanh(y) = 1 - 2/(e^{2y}+1): MUFU-based, correct at +-inf
                float t0 = 1.f - __fdividef(2.f, __expf(2.f * y0) + 1.f);
                float t1 = 1.f - __fdividef(2.f, __expf(2.f * y1) + 1.f);
                part[mt * 2 + h] += u0 * t0 + u1 * t1;
            }
        }
    }
    // reduce across the 4 lanes (lane&3) holding the same rows
#pragma unroll
    for (int q = 0; q < 4; q++) {
        part[q] += __shfl_xor_sync(0xFFFFFFFFu, part[q], 1);
        part[q] += __shfl_xor_sync(0xFFFFFFFFu, part[q], 2);
    }
    if ((lane & 3) == 0) {
        const int rr = lane >> 2;
#pragma unroll
        for (int mt = 0; mt < 2; mt++) {
            red_s[(mbase + mt * 16 + rr) * 2 + (wid & 1)]     = part[mt * 2];
            red_s[(mbase + mt * 16 + rr + 8) * 2 + (wid & 1)] = part[mt * 2 + 1];
        }
    }
    __syncthreads();

    if (tid < M_TILE) {
        float s = red_s[tid * 2] + red_s[tid * 2 + 1];
        long long row = row0 + tid;
        g_aun[row] = expf(s) * (float)mask[row];   // plain exp, matching reference
    }
}

// ---------------------------------------------------------------------------
// K2: per-batch denominator (sum over T) + EPS.
// ---------------------------------------------------------------------------
__global__ void __launch_bounds__(256) denom_kernel()
{
    __shared__ float red[8];
    const int b = blockIdx.x;
    float s = 0.f;
    for (int t = threadIdx.x; t < TT; t += 256)
        s += g_aun[(size_t)b * TT + t];
#pragma unroll
    for (int off = 16; off > 0; off >>= 1)
        s += __shfl_down_sync(0xFFFFFFFFu, s, off);
    const int warp = threadIdx.x >> 5, lane = threadIdx.x & 31;
    if (lane == 0) red[warp] = s;
    __syncthreads();
    if (threadIdx.x == 0) {
        float tot = 0.f;
#pragma unroll
        for (int w = 0; w < 8; w++) tot += red[w];
        g_denom[b] = tot + 1e-7f;
    }
}

// ---------------------------------------------------------------------------
// K3a: zero output (d_out is poisoned by harness).
// ---------------------------------------------------------------------------
__global__ void zero_kernel(float* __restrict__ out)
{
    out[blockIdx.x * blockDim.x + threadIdx.x] = 0.f;
}

// ---------------------------------------------------------------------------
// K3: out[b,e] = sum_t x[b,t,e] * a_un[b,t] / denom[b].  float4 per thread.
// ---------------------------------------------------------------------------
#define OCHUNK 128
__global__ void __launch_bounds__(256) out_kernel(
    const float* __restrict__ x, float* __restrict__ out)
{
    const int b  = blockIdx.y;
    const int t0 = blockIdx.x * OCHUNK;
    const int c4 = (threadIdx.x & 63) << 2;   // column group (4 floats)
    const int tr = threadIdx.x >> 6;          // row phase 0..3
    const float invd = 1.0f / g_denom[b];

    const float4* __restrict__ xp = (const float4*)(x + (size_t)b * TT * DD);
    const float*  __restrict__ ap = g_aun + (size_t)b * TT;

    float4 acc = make_float4(0.f, 0.f, 0.f, 0.f);
#pragma unroll 8
    for (int t = tr; t < OCHUNK; t += 4) {
        float a = ap[t0 + t];
        float4 v = xp[((size_t)(t0 + t) * DD + c4) >> 2];
        acc.x += v.x * a; acc.y += v.y * a; acc.z += v.z * a; acc.w += v.w * a;
    }
    float* o = out + b * DD + c4;
    atomicAdd(o + 0, acc.x * invd);
    atomicAdd(o + 1, acc.y * invd);
    atomicAdd(o + 2, acc.z * invd);
    atomicAdd(o + 3, acc.w * invd);
}

// ---------------------------------------------------------------------------
extern "C" void kernel_launch(void* const* d_in, const int* in_sizes, int n_in,
                              void* d_out, int out_size)
{
    const float* x    = (const float*)d_in[0];
    const float* W    = (const float*)d_in[1];
    const float* bias = (const float*)d_in[2];
    const float* uw   = (const float*)d_in[3];
    const int*   mask = (const int*)d_in[4];
    float* out = (float*)d_out;

    cudaFuncSetAttribute(scores_mma_kernel,
                         cudaFuncAttributeMaxDynamicSharedMemorySize, SMEM_SC);

    prep_w_kernel<<<DD, 256>>>(W);
    scores_mma_kernel<<<(BB * TT) / M_TILE, THREADS_SC, SMEM_SC>>>(x, bias, uw, mask);
    denom_kernel<<<BB, 256>>>();
    zero_kernel<<<(BB * DD) / 256, 256>>>(out);
    out_kernel<<<dim3(TT / OCHUNK, BB), 256>>>(x, out);
}

// round 9
// speedup vs baseline: 3.1184x; 1.4299x over previous
#include <cuda_runtime.h>
#include <cuda_bf16.h>
#include <math.h>
#include <stdint.h>

// Problem dims (fixed by dataset)
#define BB 64
#define TT 2048
#define DD 256

// scores kernel tiling (mma.sync path: tcgen05 not reachable — harness lowers
// through compute_103 virtual arch, which rejects all 'a'-gated instructions)
#define M_TILE 128        // rows per CTA
#define KC 64             // K chunk (bf16 row = 128B swizzle atom)
#define NCH 4             // DD / KC
#define THREADS_SC 256    // 8 warps

// dynamic smem: two 96KB stages + tail arrays
#define STG      98304
#define S_AH     0          // 128 x 64 bf16 = 16 KB
#define S_AL     16384
#define S_WH     32768      // 256 x 64 bf16 = 32 KB
#define S_WL     65536
#define OFF_RED  196608     // 128 x 2 fp32
#define OFF_UW   197632
#define OFF_BIAS 198656
#define SMEM_SC  199680

// ---------------------------------------------------------------------------
// device scratch (allocation-free rule: __device__ globals)
// ---------------------------------------------------------------------------
__device__ float g_aun[BB * TT];                 // exp(s) * mask
__device__ float g_denom[BB];                    // per-batch sum (EPS added at use)
__device__ __nv_bfloat16 g_Whi[NCH * DD * KC];   // W^T hi, pre-swizzled chunks
__device__ __nv_bfloat16 g_Wlo[NCH * DD * KC];   // W^T lo, pre-swizzled chunks

// ---------------------------------------------------------------------------
// helpers
// ---------------------------------------------------------------------------
__device__ __forceinline__ uint32_t smem_u32(const void* p) {
    uint32_t a;
    asm("{ .reg .u64 t; cvta.to.shared.u64 t, %1; cvt.u32.u64 %0, t; }"
        : "=r"(a) : "l"(p));
    return a;
}

#define SWZ(off) ((off) ^ (((off) >> 3) & 0x70))

__device__ __forceinline__ uint32_t pkbf2(float a, float b) {
    __nv_bfloat162 h = __floats2bfloat162_rn(a, b);   // .x (low) = a
    return *reinterpret_cast<uint32_t*>(&h);
}

__device__ __forceinline__ void ldsm_x4(uint32_t* q, uint32_t addr) {
    asm volatile("ldmatrix.sync.aligned.m8n8.x4.shared.b16 {%0,%1,%2,%3}, [%4];"
                 : "=r"(q[0]), "=r"(q[1]), "=r"(q[2]), "=r"(q[3]) : "r"(addr));
}

__device__ __forceinline__ void mma_16816(float* d, const uint32_t* a,
                                          uint32_t b0, uint32_t b1) {
    asm volatile(
        "mma.sync.aligned.m16n8k16.row.col.f32.bf16.bf16.f32 "
        "{%0,%1,%2,%3}, {%4,%5,%6,%7}, {%8,%9}, {%0,%1,%2,%3};"
        : "+f"(d[0]), "+f"(d[1]), "+f"(d[2]), "+f"(d[3])
        : "r"(a[0]), "r"(a[1]), "r"(a[2]), "r"(a[3]), "r"(b0), "r"(b1));
}

__device__ __forceinline__ void cp16(uint32_t saddr, const void* g) {
    asm volatile("cp.async.cg.shared.global [%0], [%1], 16;"
                 :: "r"(saddr), "l"(g) : "memory");
}

// ---------------------------------------------------------------------------
// pre: zero out (poisoned) and g_denom accumulators
// ---------------------------------------------------------------------------
__global__ void __launch_bounds__(256) pre_kernel(float* __restrict__ out)
{
    out[blockIdx.x * 256 + threadIdx.x] = 0.f;
    if (blockIdx.x == 0 && threadIdx.x < BB) g_denom[threadIdx.x] = 0.f;
}

// ---------------------------------------------------------------------------
// prep: W^T split into bf16 hi/lo, stored as pre-swizzled 32KB chunk images
// ---------------------------------------------------------------------------
__global__ void __launch_bounds__(256) prep_w_kernel(const float* __restrict__ W)
{
    const int d = blockIdx.x;    // K index
    const int e = threadIdx.x;   // N index
    float w = W[d * DD + e];
    __nv_bfloat16 h = __float2bfloat16(w);
    __nv_bfloat16 l = __float2bfloat16(w - __bfloat162float(h));
    const int kc = d >> 6, dl = d & 63;
    uint32_t sw = SWZ((uint32_t)(e * 128 + dl * 2));
    g_Whi[kc * (DD * KC) + (sw >> 1)] = h;
    g_Wlo[kc * (DD * KC) + (sw >> 1)] = l;
}

// ---------------------------------------------------------------------------
// K1: scores via mma.sync bf16x3, software-pipelined (cp.async W, reg-prefetch x).
// Per CTA: y[128,256] = x @ W; s = sum_e uw_e*tanh(y+b); g_aun = exp(s)*mask;
// block-reduced sum of g_aun atomically added to g_denom[b].
// ---------------------------------------------------------------------------
__global__ void __launch_bounds__(THREADS_SC, 1) scores_mma_kernel(
    const float* __restrict__ x, const float* __restrict__ bias,
    const float* __restrict__ uw, const int* __restrict__ mask)
{
    extern __shared__ char smem[];
    const uint32_t sb = smem_u32(smem);
    const int tid  = threadIdx.x;
    const int wid  = tid >> 5;
    const int lane = tid & 31;

    const int mbase = (wid >> 1) * 32;       // warp's row base
    const int ncol0 = (wid & 1) * 128;       // warp's col base

    float* red_s  = (float*)(smem + OFF_RED);
    float* uw_s   = (float*)(smem + OFF_UW);
    float* bias_s = (float*)(smem + OFF_BIAS);
    for (int i = tid; i < DD; i += THREADS_SC) { uw_s[i] = uw[i]; bias_s[i] = bias[i]; }

    const long long row0 = (long long)blockIdx.x * M_TILE;
    const float4* __restrict__ x4 = (const float4*)(x + row0 * DD);

    // per-thread staging indices (8 float4 / 16B segs per thread)
    const int r_st  = tid >> 4;          // base row (stride 16 over j)
    const int seg   = tid & 15;
    const uint32_t sw_st = SWZ((uint32_t)(r_st * 128 + seg * 8));

    // ---- staging lambdas (manually inlined) ----
    // W chunk kc -> stage s (cp.async, pre-swizzled linear images)
    // x chunk kc -> regs; regs -> stage s (convert + STS)

    float4 xr[8];

    // prologue: stage chunk 0
    {
        const char* wh = (const char*)(g_Whi + 0 * (DD * KC));
        const char* wl = (const char*)(g_Wlo + 0 * (DD * KC));
#pragma unroll
        for (int j = 0; j < 8; j++) {
            cp16(sb + S_WH + (tid + 256 * j) * 16, wh + (tid + 256 * j) * 16);
            cp16(sb + S_WL + (tid + 256 * j) * 16, wl + (tid + 256 * j) * 16);
        }
        asm volatile("cp.async.commit_group;" ::: "memory");
#pragma unroll
        for (int j = 0; j < 8; j++)
            xr[j] = x4[(r_st + 16 * j) * (DD / 4) + seg];
#pragma unroll
        for (int j = 0; j < 8; j++) {
            float4 v = xr[j];
            float hx = __bfloat162float(__float2bfloat16(v.x));
            float hy = __bfloat162float(__float2bfloat16(v.y));
            float hz = __bfloat162float(__float2bfloat16(v.z));
            float hw = __bfloat162float(__float2bfloat16(v.w));
            uint32_t swo = SWZ((uint32_t)((r_st + 16 * j) * 128 + seg * 8));
            *(uint2*)(smem + S_AH + swo) = make_uint2(pkbf2(v.x, v.y), pkbf2(v.z, v.w));
            *(uint2*)(smem + S_AL + swo) =
                make_uint2(pkbf2(v.x - hx, v.y - hy), pkbf2(v.z - hz, v.w - hw));
        }
        asm volatile("cp.async.wait_group 0;" ::: "memory");
        __syncthreads();
    }

    float acc[2][16][4];
#pragma unroll
    for (int mt = 0; mt < 2; mt++)
#pragma unroll
        for (int j = 0; j < 16; j++)
#pragma unroll
            for (int v = 0; v < 4; v++) acc[mt][j][v] = 0.f;

    // per-lane ldmatrix address components (x4 lane-group layout)
    const int r_a = (lane & 7) + ((lane >> 3) & 1) * 8;   // A: row within m16
    const int k_a = (lane >> 4) * 8;                      // A: k offset
    const int r_b = (lane & 7) + ((lane >> 4) & 1) * 8;   // B: n within pair
    const int k_b = ((lane >> 3) & 1) * 8;                // B: k offset

    for (int kc = 0; kc < NCH; kc++) {
        const uint32_t cb = sb + (uint32_t)(kc & 1) * STG;      // current stage
        const uint32_t nb = sb + (uint32_t)((kc & 1) ^ 1) * STG; // next stage
        const char* nsm = smem + (size_t)((kc & 1) ^ 1) * STG;

        if (kc < NCH - 1) {
            // issue next W cp.async + next x LDGs (latency hidden under MMAs)
            const char* wh = (const char*)(g_Whi + (kc + 1) * (DD * KC));
            const char* wl = (const char*)(g_Wlo + (kc + 1) * (DD * KC));
#pragma unroll
            for (int j = 0; j < 8; j++) {
                cp16(nb + S_WH + (tid + 256 * j) * 16, wh + (tid + 256 * j) * 16);
                cp16(nb + S_WL + (tid + 256 * j) * 16, wl + (tid + 256 * j) * 16);
            }
            asm volatile("cp.async.commit_group;" ::: "memory");
#pragma unroll
            for (int j = 0; j < 8; j++)
                xr[j] = x4[(r_st + 16 * j) * (DD / 4) + (kc + 1) * (KC / 4) + seg];
        }

        // --- compute: 4 K16 steps x (2 m-tiles x 16 n-tiles) x 3 products ---
#pragma unroll
        for (int ks = 0; ks < 4; ks++) {
            const int kk = ks * 16;
            uint32_t ah[2][4], al[2][4];
#pragma unroll
            for (int mt = 0; mt < 2; mt++) {
                uint32_t ao = SWZ((uint32_t)((mbase + mt * 16 + r_a) * 128 + (kk + k_a) * 2));
                ldsm_x4(ah[mt], cb + S_AH + ao);
                ldsm_x4(al[mt], cb + S_AL + ao);
            }
#pragma unroll
            for (int p = 0; p < 8; p++) {
                uint32_t bo = SWZ((uint32_t)((ncol0 + p * 16 + r_b) * 128 + (kk + k_b) * 2));
                uint32_t bh[4], bl[4];
                ldsm_x4(bh, cb + S_WH + bo);
                ldsm_x4(bl, cb + S_WL + bo);
#pragma unroll
                for (int mt = 0; mt < 2; mt++) {
                    mma_16816(acc[mt][2 * p],     ah[mt], bh[0], bh[1]);
                    mma_16816(acc[mt][2 * p + 1], ah[mt], bh[2], bh[3]);
                    mma_16816(acc[mt][2 * p],     al[mt], bh[0], bh[1]);
                    mma_16816(acc[mt][2 * p + 1], al[mt], bh[2], bh[3]);
                    mma_16816(acc[mt][2 * p],     ah[mt], bl[0], bl[1]);
                    mma_16816(acc[mt][2 * p + 1], ah[mt], bl[2], bl[3]);
                }
            }
        }

        if (kc < NCH - 1) {
            // convert prefetched x into next stage; then drain cp.async
#pragma unroll
            for (int j = 0; j < 8; j++) {
                float4 v = xr[j];
                float hx = __bfloat162float(__float2bfloat16(v.x));
                float hy = __bfloat162float(__float2bfloat16(v.y));
                float hz = __bfloat162float(__float2bfloat16(v.z));
                float hw = __bfloat162float(__float2bfloat16(v.w));
                uint32_t swo = SWZ((uint32_t)((r_st + 16 * j) * 128 + seg * 8));
                *(uint2*)(nsm + S_AH + swo) = make_uint2(pkbf2(v.x, v.y), pkbf2(v.z, v.w));
                *(uint2*)(nsm + S_AL + swo) =
                    make_uint2(pkbf2(v.x - hx, v.y - hy), pkbf2(v.z - hz, v.w - hw));
            }
            asm volatile("cp.async.wait_group 0;" ::: "memory");
        }
        __syncthreads();
    }

    // --- epilogue: tanh + uw-dot on fragments ---
    float part[4] = {0.f, 0.f, 0.f, 0.f};
#pragma unroll
    for (int mt = 0; mt < 2; mt++) {
#pragma unroll
        for (int j = 0; j < 16; j++) {
            const int C = ncol0 + j * 8 + (lane & 3) * 2;
            const float u0 = uw_s[C], u1 = uw_s[C + 1];
            const float b0 = bias_s[C], b1 = bias_s[C + 1];
#pragma unroll
            for (int h = 0; h < 2; h++) {
                float y0 = acc[mt][j][2 * h]     + b0;
                float y1 = acc[mt][j][2 * h + 1] + b1;
                float t0 = 1.f - __fdividef(2.f, __expf(2.f * y0) + 1.f);
                float t1 = 1.f - __fdividef(2.f, __expf(2.f * y1) + 1.f);
                part[mt * 2 + h] += u0 * t0 + u1 * t1;
            }
        }
    }
#pragma unroll
    for (int q = 0; q < 4; q++) {
        part[q] += __shfl_xor_sync(0xFFFFFFFFu, part[q], 1);
        part[q] += __shfl_xor_sync(0xFFFFFFFFu, part[q], 2);
    }
    if ((lane & 3) == 0) {
        const int rr = lane >> 2;
#pragma unroll
        for (int mt = 0; mt < 2; mt++) {
            red_s[(mbase + mt * 16 + rr) * 2 + (wid & 1)]     = part[mt * 2];
            red_s[(mbase + mt * 16 + rr + 8) * 2 + (wid & 1)] = part[mt * 2 + 1];
        }
    }
    __syncthreads();

    float aval = 0.f;
    if (tid < M_TILE) {
        float s = red_s[tid * 2] + red_s[tid * 2 + 1];
        long long row = row0 + tid;
        aval = expf(s) * (float)mask[row];
        g_aun[row] = aval;
    }
    // block-reduce aval over tid<128 -> atomic add into g_denom[b]
#pragma unroll
    for (int off = 16; off > 0; off >>= 1)
        aval += __shfl_down_sync(0xFFFFFFFFu, aval, off);
    if (lane == 0) red_s[wid] = aval;   // red_s reuse (post-sync)
    __syncthreads();
    if (tid == 0) {
        float tot = red_s[0] + red_s[1] + red_s[2] + red_s[3];
        atomicAdd(&g_denom[row0 / TT], tot);
    }
}

// ---------------------------------------------------------------------------
// K3: out[b,e] = sum_t x[b,t,e] * a_un[b,t] / (denom[b]+EPS). float4/thread.
// ---------------------------------------------------------------------------
#define OCHUNK 128
__global__ void __launch_bounds__(256) out_kernel(
    const float* __restrict__ x, float* __restrict__ out)
{
    const int b  = blockIdx.y;
    const int t0 = blockIdx.x * OCHUNK;
    const int c4 = (threadIdx.x & 63) << 2;   // column group (4 floats)
    const int tr = threadIdx.x >> 6;          // row phase 0..3
    const float invd = 1.0f / (g_denom[b] + 1e-7f);

    const float4* __restrict__ xp = (const float4*)(x + (size_t)b * TT * DD);
    const float*  __restrict__ ap = g_aun + (size_t)b * TT;

    float4 acc = make_float4(0.f, 0.f, 0.f, 0.f);
#pragma unroll 16
    for (int t = tr; t < OCHUNK; t += 4) {
        float a = ap[t0 + t];
        float4 v = __ldcs(&xp[((size_t)(t0 + t) * DD + c4) >> 2]);
        acc.x += v.x * a; acc.y += v.y * a; acc.z += v.z * a; acc.w += v.w * a;
    }
    float* o = out + b * DD + c4;
    atomicAdd(o + 0, acc.x * invd);
    atomicAdd(o + 1, acc.y * invd);
    atomicAdd(o + 2, acc.z * invd);
    atomicAdd(o + 3, acc.w * invd);
}

// ---------------------------------------------------------------------------
extern "C" void kernel_launch(void* const* d_in, const int* in_sizes, int n_in,
                              void* d_out, int out_size)
{
    const float* x    = (const float*)d_in[0];
    const float* W    = (const float*)d_in[1];
    const float* bias = (const float*)d_in[2];
    const float* uw   = (const float*)d_in[3];
    const int*   mask = (const int*)d_in[4];
    float* out = (float*)d_out;

    cudaFuncSetAttribute(scores_mma_kernel,
                         cudaFuncAttributeMaxDynamicSharedMemorySize, SMEM_SC);

    pre_kernel<<<(BB * DD) / 256, 256>>>(out);
    prep_w_kernel<<<DD, 256>>>(W);
    scores_mma_kernel<<<(BB * TT) / M_TILE, THREADS_SC, SMEM_SC>>>(x, bias, uw, mask);
    out_kernel<<<dim3(TT / OCHUNK, BB), 256>>>(x, out);
}

// round 12
// speedup vs baseline: 3.9489x; 1.2663x over previous
#include <cuda_runtime.h>
#include <cuda_fp16.h>
#include <math.h>
#include <stdint.h>

// Problem dims (fixed by dataset)
#define BB 64
#define TT 2048
#define DD 256

// scores kernel tiling (mma.sync path: tcgen05 not reachable on compute_103)
#define M_TILE 128        // rows per CTA
#define KC 64             // K chunk (fp16 row = 128B swizzle atom)
#define NCH 4             // DD / KC
#define THREADS_SC 256    // 8 warps

// dynamic smem: two 96KB stages + tail arrays
#define STG      98304
#define S_A      0          // 128 x 64 fp16 = 16 KB  (A = fp16(x))
#define S_A2     16384      //                      (A2 = fp16(x * 2^-12))
#define S_WH     32768      // 256 x 64 fp16 = 32 KB (Wh = fp16(W))
#define S_WL     65536      //                      (Wl' = fp16((W-Wh)*2^12))
#define OFF_RED  196608     // 128 x 2 fp32
#define OFF_UW   197632
#define OFF_BIAS 198656
#define SMEM_SC  199680

#define A2SCALE 2.44140625e-4f   // 2^-12

// ---------------------------------------------------------------------------
// device scratch (allocation-free rule: __device__ globals)
// ---------------------------------------------------------------------------
__device__ float g_aun[BB * TT];            // exp(s) * mask
__device__ float g_denom[BB];               // per-batch sum (EPS added at use)
__device__ __half g_Whi[NCH * DD * KC];     // W^T hi, pre-swizzled chunks
__device__ __half g_Wlo[NCH * DD * KC];     // W^T residual * 2^12, pre-swizzled

// ---------------------------------------------------------------------------
// helpers
// ---------------------------------------------------------------------------
__device__ __forceinline__ uint32_t smem_u32(const void* p) {
    uint32_t a;
    asm("{ .reg .u64 t; cvta.to.shared.u64 t, %1; cvt.u32.u64 %0, t; }"
        : "=r"(a) : "l"(p));
    return a;
}

#define SWZ(off) ((off) ^ (((off) >> 3) & 0x70))

__device__ __forceinline__ uint32_t pkh2(float a, float b) {
    __half2 h = __floats2half2_rn(a, b);   // .x (low) = a
    return *reinterpret_cast<uint32_t*>(&h);
}

__device__ __forceinline__ void ldsm_x4(uint32_t* q, uint32_t addr) {
    asm volatile("ldmatrix.sync.aligned.m8n8.x4.shared.b16 {%0,%1,%2,%3}, [%4];"
                 : "=r"(q[0]), "=r"(q[1]), "=r"(q[2]), "=r"(q[3]) : "r"(addr));
}

__device__ __forceinline__ void mma_16816(float* d, const uint32_t* a,
                                          uint32_t b0, uint32_t b1) {
    asm volatile(
        "mma.sync.aligned.m16n8k16.row.col.f32.f16.f16.f32 "
        "{%0,%1,%2,%3}, {%4,%5,%6,%7}, {%8,%9}, {%0,%1,%2,%3};"
        : "+f"(d[0]), "+f"(d[1]), "+f"(d[2]), "+f"(d[3])
        : "r"(a[0]), "r"(a[1]), "r"(a[2]), "r"(a[3]), "r"(b0), "r"(b1));
}

__device__ __forceinline__ void cp16(uint32_t saddr, const void* g) {
    asm volatile("cp.async.cg.shared.global [%0], [%1], 16;"
                 :: "r"(saddr), "l"(g) : "memory");
}

// ---------------------------------------------------------------------------
// pre: zero out (poisoned) and g_denom accumulators
// ---------------------------------------------------------------------------
__global__ void __launch_bounds__(256) pre_kernel(float* __restrict__ out)
{
    out[blockIdx.x * 256 + threadIdx.x] = 0.f;
    if (blockIdx.x == 0 && threadIdx.x < BB) g_denom[threadIdx.x] = 0.f;
}

// ---------------------------------------------------------------------------
// prep: W^T -> fp16 hi + scaled residual, pre-swizzled 32KB chunk images
// ---------------------------------------------------------------------------
__global__ void __launch_bounds__(256) prep_w_kernel(const float* __restrict__ W)
{
    const int d = blockIdx.x;    // K index
    const int e = threadIdx.x;   // N index
    float w = W[d * DD + e];
    __half h = __float2half_rn(w);
    __half l = __float2half_rn((w - __half2float(h)) * 4096.0f);  // *2^12: keeps residual normal-range
    const int kc = d >> 6, dl = d & 63;
    uint32_t sw = SWZ((uint32_t)(e * 128 + dl * 2));
    g_Whi[kc * (DD * KC) + (sw >> 1)] = h;
    g_Wlo[kc * (DD * KC) + (sw >> 1)] = l;
}

// ---------------------------------------------------------------------------
// K1: scores via mma.sync fp16x2, software-pipelined (cp.async W, reg-prefetch x).
// y = A*Wh + (A*2^-12)*(Wres*2^12)  (scales cancel in-product; fp32 accum).
// Then s = sum_e uw_e*tanh(y+b); g_aun = exp(s)*mask; block denom -> atomic.
// ---------------------------------------------------------------------------
__global__ void __launch_bounds__(THREADS_SC, 1) scores_mma_kernel(
    const float* __restrict__ x, const float* __restrict__ bias,
    const float* __restrict__ uw, const int* __restrict__ mask)
{
    extern __shared__ char smem[];
    const uint32_t sb = smem_u32(smem);
    const int tid  = threadIdx.x;
    const int wid  = tid >> 5;
    const int lane = tid & 31;

    const int mbase = (wid >> 1) * 32;       // warp's row base
    const int ncol0 = (wid & 1) * 128;       // warp's col base

    float* red_s  = (float*)(smem + OFF_RED);
    float* uw_s   = (float*)(smem + OFF_UW);
    float* bias_s = (float*)(smem + OFF_BIAS);
    for (int i = tid; i < DD; i += THREADS_SC) { uw_s[i] = uw[i]; bias_s[i] = bias[i]; }

    const long long row0 = (long long)blockIdx.x * M_TILE;
    const float4* __restrict__ x4 = (const float4*)(x + row0 * DD);

    // per-thread staging indices (8 float4 / 16B segs per thread)
    const int r_st  = tid >> 4;          // base row (stride 16 over j)
    const int seg   = tid & 15;

    float4 xr[8];

    // prologue: stage chunk 0
    {
        const char* wh = (const char*)(g_Whi + 0 * (DD * KC));
        const char* wl = (const char*)(g_Wlo + 0 * (DD * KC));
#pragma unroll
        for (int j = 0; j < 8; j++) {
            cp16(sb + S_WH + (tid + 256 * j) * 16, wh + (tid + 256 * j) * 16);
            cp16(sb + S_WL + (tid + 256 * j) * 16, wl + (tid + 256 * j) * 16);
        }
        asm volatile("cp.async.commit_group;" ::: "memory");
#pragma unroll
        for (int j = 0; j < 8; j++)
            xr[j] = x4[(r_st + 16 * j) * (DD / 4) + seg];
#pragma unroll
        for (int j = 0; j < 8; j++) {
            float4 v = xr[j];
            uint32_t swo = SWZ((uint32_t)((r_st + 16 * j) * 128 + seg * 8));
            *(uint2*)(smem + S_A  + swo) = make_uint2(pkh2(v.x, v.y), pkh2(v.z, v.w));
            *(uint2*)(smem + S_A2 + swo) =
                make_uint2(pkh2(v.x * A2SCALE, v.y * A2SCALE),
                           pkh2(v.z * A2SCALE, v.w * A2SCALE));
        }
        asm volatile("cp.async.wait_group 0;" ::: "memory");
        __syncthreads();
    }

    float acc[2][16][4];
#pragma unroll
    for (int mt = 0; mt < 2; mt++)
#pragma unroll
        for (int j = 0; j < 16; j++)
#pragma unroll
            for (int v = 0; v < 4; v++) acc[mt][j][v] = 0.f;

    // per-lane ldmatrix address components (x4 lane-group layout)
    const int r_a = (lane & 7) + ((lane >> 3) & 1) * 8;   // A: row within m16
    const int k_a = (lane >> 4) * 8;                      // A: k offset
    const int r_b = (lane & 7) + ((lane >> 4) & 1) * 8;   // B: n within pair
    const int k_b = ((lane >> 3) & 1) * 8;                // B: k offset

    for (int kc = 0; kc < NCH; kc++) {
        const uint32_t cb = sb + (uint32_t)(kc & 1) * STG;       // current stage
        const uint32_t nb = sb + (uint32_t)((kc & 1) ^ 1) * STG; // next stage
        const char* nsm = smem + (size_t)((kc & 1) ^ 1) * STG;

        if (kc < NCH - 1) {
            const char* wh = (const char*)(g_Whi + (kc + 1) * (DD * KC));
            const char* wl = (const char*)(g_Wlo + (kc + 1) * (DD * KC));
#pragma unroll
            for (int j = 0; j < 8; j++) {
                cp16(nb + S_WH + (tid + 256 * j) * 16, wh + (tid + 256 * j) * 16);
                cp16(nb + S_WL + (tid + 256 * j) * 16, wl + (tid + 256 * j) * 16);
            }
            asm volatile("cp.async.commit_group;" ::: "memory");
#pragma unroll
            for (int j = 0; j < 8; j++)
                xr[j] = x4[(r_st + 16 * j) * (DD / 4) + (kc + 1) * (KC / 4) + seg];
        }

        // --- compute: 4 K16 steps x (2 m-tiles x 16 n-tiles) x 2 products ---
#pragma unroll
        for (int ks = 0; ks < 4; ks++) {
            const int kk = ks * 16;
            uint32_t ah[2][4], a2[2][4];
#pragma unroll
            for (int mt = 0; mt < 2; mt++) {
                uint32_t ao = SWZ((uint32_t)((mbase + mt * 16 + r_a) * 128 + (kk + k_a) * 2));
                ldsm_x4(ah[mt], cb + S_A  + ao);
                ldsm_x4(a2[mt], cb + S_A2 + ao);
            }
#pragma unroll
            for (int p = 0; p < 8; p++) {
                uint32_t bo = SWZ((uint32_t)((ncol0 + p * 16 + r_b) * 128 + (kk + k_b) * 2));
                uint32_t bh[4], bl[4];
                ldsm_x4(bh, cb + S_WH + bo);
                ldsm_x4(bl, cb + S_WL + bo);
#pragma unroll
                for (int mt = 0; mt < 2; mt++) {
                    mma_16816(acc[mt][2 * p],     ah[mt], bh[0], bh[1]);
                    mma_16816(acc[mt][2 * p + 1], ah[mt], bh[2], bh[3]);
                    mma_16816(acc[mt][2 * p],     a2[mt], bl[0], bl[1]);
                    mma_16816(acc[mt][2 * p + 1], a2[mt], bl[2], bl[3]);
                }
            }
        }

        if (kc < NCH - 1) {
            // convert prefetched x into next stage; then drain cp.async
#pragma unroll
            for (int j = 0; j < 8; j++) {
                float4 v = xr[j];
                uint32_t swo = SWZ((uint32_t)((r_st + 16 * j) * 128 + seg * 8));
                *(uint2*)(nsm + S_A  + swo) = make_uint2(pkh2(v.x, v.y), pkh2(v.z, v.w));
                *(uint2*)(nsm + S_A2 + swo) =
                    make_uint2(pkh2(v.x * A2SCALE, v.y * A2SCALE),
                               pkh2(v.z * A2SCALE, v.w * A2SCALE));
            }
            asm volatile("cp.async.wait_group 0;" ::: "memory");
        }
        __syncthreads();
    }

    // --- epilogue: tanh + uw-dot on fragments ---
    float part[4] = {0.f, 0.f, 0.f, 0.f};
#pragma unroll
    for (int mt = 0; mt < 2; mt++) {
#pragma unroll
        for (int j = 0; j < 16; j++) {
            const int C = ncol0 + j * 8 + (lane & 3) * 2;
            const float u0 = uw_s[C], u1 = uw_s[C + 1];
            const float b0 = bias_s[C], b1 = bias_s[C + 1];
#pragma unroll
            for (int h = 0; h < 2; h++) {
                float y0 = acc[mt][j][2 * h]     + b0;
                float y1 = acc[mt][j][2 * h + 1] + b1;
                float t0 = 1.f - __fdividef(2.f, __expf(2.f * y0) + 1.f);
                float t1 = 1.f - __fdividef(2.f, __expf(2.f * y1) + 1.f);
                part[mt * 2 + h] += u0 * t0 + u1 * t1;
            }
        }
    }
#pragma unroll
    for (int q = 0; q < 4; q++) {
        part[q] += __shfl_xor_sync(0xFFFFFFFFu, part[q], 1);
        part[q] += __shfl_xor_sync(0xFFFFFFFFu, part[q], 2);
    }
    if ((lane & 3) == 0) {
        const int rr = lane >> 2;
#pragma unroll
        for (int mt = 0; mt < 2; mt++) {
            red_s[(mbase + mt * 16 + rr) * 2 + (wid & 1)]     = part[mt * 2];
            red_s[(mbase + mt * 16 + rr + 8) * 2 + (wid & 1)] = part[mt * 2 + 1];
        }
    }
    __syncthreads();

    float aval = 0.f;
    if (tid < M_TILE) {
        float s = red_s[tid * 2] + red_s[tid * 2 + 1];
        long long row = row0 + tid;
        aval = expf(s) * (float)mask[row];
        g_aun[row] = aval;
    }
    // block-reduce aval over tid<128 -> atomic add into g_denom[b]
#pragma unroll
    for (int off = 16; off > 0; off >>= 1)
        aval += __shfl_down_sync(0xFFFFFFFFu, aval, off);
    if (lane == 0) red_s[wid] = aval;   // red_s reuse (post-sync)
    __syncthreads();
    if (tid == 0) {
        float tot = red_s[0] + red_s[1] + red_s[2] + red_s[3];
        atomicAdd(&g_denom[row0 / TT], tot);
    }
}

// ---------------------------------------------------------------------------
// K3: out[b,e] = sum_t x[b,t,e] * a_un[b,t] / (denom[b]+EPS).
// (R3 scalar form: regs=19, occ 80%, 60% DRAM — best measured variant.)
// ---------------------------------------------------------------------------
#define OCHUNK 128
__global__ void __launch_bounds__(256) out_kernel(
    const float* __restrict__ x, float* __restrict__ out)
{
    const int b = blockIdx.y;
    const int e = threadIdx.x;
    const int t0 = blockIdx.x * OCHUNK;
    const float invd = 1.0f / (g_denom[b] + 1e-7f);

    float acc = 0.f;
    const float* __restrict__ xp = x + ((size_t)b * TT + t0) * DD + e;
    const float* __restrict__ ap = g_aun + (size_t)b * TT + t0;
#pragma unroll 4
    for (int t = 0; t < OCHUNK; t++) {
        acc += xp[(size_t)t * DD] * ap[t];
    }
    atomicAdd(&out[b * DD + e], acc * invd);
}

// ---------------------------------------------------------------------------
extern "C" void kernel_launch(void* const* d_in, const int* in_sizes, int n_in,
                              void* d_out, int out_size)
{
    const float* x    = (const float*)d_in[0];
    const float* W    = (const float*)d_in[1];
    const float* bias = (const float*)d_in[2];
    const float* uw   = (const float*)d_in[3];
    const int*   mask = (const int*)d_in[4];
    float* out = (float*)d_out;

    cudaFuncSetAttribute(scores_mma_kernel,
                         cudaFuncAttributeMaxDynamicSharedMemorySize, SMEM_SC);

    pre_kernel<<<(BB * DD) / 256, 256>>>(out);
    prep_w_kernel<<<DD, 256>>>(W);
    scores_mma_kernel<<<(BB * TT) / M_TILE, THREADS_SC, SMEM_SC>>>(x, bias, uw, mask);
    out_kernel<<<dim3(TT / OCHUNK, BB), 256>>>(x, out);
}

// round 15
// speedup vs baseline: 4.0160x; 1.0170x over previous
#include <cuda_runtime.h>
#include <cuda_fp16.h>
#include <math.h>
#include <stdint.h>

// Problem dims (fixed by dataset)
#define BB 64
#define TT 2048
#define DD 256

// scores kernel tiling (mma.sync path: tcgen05 not reachable on compute_103)
#define M_TILE 64         // rows per CTA (small tile -> 2 CTAs/SM overlap)
#define KC 64             // K chunk (fp16 row = 128B swizzle atom)
#define NCH 4             // DD / KC
#define THREADS_SC 256    // 8 warps: 2 m-halves x 4 n-quarters

// single-stage dynamic smem (fits 2 CTAs/SM: ~85KB each)
#define S_A      0          // 64 x 64 fp16 = 8 KB   (A = fp16(x))
#define S_A2     8192       //                      (A2 = fp16(x * 2^-12))
#define S_WH     16384      // 256 x 64 fp16 = 32 KB (Wh = fp16(W))
#define S_WL     49152      //                      (Wl' = fp16((W-Wh)*2^12))
#define OFF_RED  81920      // 64 rows x 4 n-warp partials fp32 = 1 KB
#define OFF_UW   82944
#define OFF_BIAS 83968
#define OFF_AUN  84992      // 64 fp32
#define SMEM_SC  85504

#define A2SCALE 2.44140625e-4f   // 2^-12

// ---------------------------------------------------------------------------
// device scratch (allocation-free rule: __device__ globals)
// ---------------------------------------------------------------------------
__device__ float g_aun[BB * TT];            // exp(s) * mask (kept for debug/denom path)
__device__ float g_denom[BB];               // per-batch sum (EPS added at use)
__device__ float g_outacc[BB * DD];         // unnormalized out accumulators
__device__ __half g_Whi[NCH * DD * KC];     // W^T hi, pre-swizzled chunks
__device__ __half g_Wlo[NCH * DD * KC];     // W^T residual * 2^12, pre-swizzled

// ---------------------------------------------------------------------------
// helpers
// ---------------------------------------------------------------------------
__device__ __forceinline__ uint32_t smem_u32(const void* p) {
    uint32_t a;
    asm("{ .reg .u64 t; cvta.to.shared.u64 t, %1; cvt.u32.u64 %0, t; }"
        : "=r"(a) : "l"(p));
    return a;
}

#define SWZ(off) ((off) ^ (((off) >> 3) & 0x70))

__device__ __forceinline__ uint32_t pkh2(float a, float b) {
    __half2 h = __floats2half2_rn(a, b);   // .x (low) = a
    return *reinterpret_cast<uint32_t*>(&h);
}

__device__ __forceinline__ void ldsm_x4(uint32_t* q, uint32_t addr) {
    asm volatile("ldmatrix.sync.aligned.m8n8.x4.shared.b16 {%0,%1,%2,%3}, [%4];"
                 : "=r"(q[0]), "=r"(q[1]), "=r"(q[2]), "=r"(q[3]) : "r"(addr));
}

__device__ __forceinline__ void mma_16816(float* d, const uint32_t* a,
                                          uint32_t b0, uint32_t b1) {
    asm volatile(
        "mma.sync.aligned.m16n8k16.row.col.f32.f16.f16.f32 "
        "{%0,%1,%2,%3}, {%4,%5,%6,%7}, {%8,%9}, {%0,%1,%2,%3};"
        : "+f"(d[0]), "+f"(d[1]), "+f"(d[2]), "+f"(d[3])
        : "r"(a[0]), "r"(a[1]), "r"(a[2]), "r"(a[3]), "r"(b0), "r"(b1));
}

__device__ __forceinline__ void cp16(uint32_t saddr, const void* g) {
    asm volatile("cp.async.cg.shared.global [%0], [%1], 16;"
                 :: "r"(saddr), "l"(g) : "memory");
}

// ---------------------------------------------------------------------------
// pre: zero g_outacc + g_denom
// ---------------------------------------------------------------------------
__global__ void __launch_bounds__(256) pre_kernel()
{
    g_outacc[blockIdx.x * 256 + threadIdx.x] = 0.f;
    if (blockIdx.x == 0 && threadIdx.x < BB) g_denom[threadIdx.x] = 0.f;
}

// ---------------------------------------------------------------------------
// prep: W^T -> fp16 hi + scaled residual, pre-swizzled 32KB chunk images
// ---------------------------------------------------------------------------
__global__ void __launch_bounds__(256) prep_w_kernel(const float* __restrict__ W)
{
    const int d = blockIdx.x;    // K index
    const int e = threadIdx.x;   // N index
    float w = W[d * DD + e];
    __half h = __float2half_rn(w);
    __half l = __float2half_rn((w - __half2float(h)) * 4096.0f);  // *2^12 keeps residual normal-range
    const int kc = d >> 6, dl = d & 63;
    uint32_t sw = SWZ((uint32_t)(e * 128 + dl * 2));
    g_Whi[kc * (DD * KC) + (sw >> 1)] = h;
    g_Wlo[kc * (DD * KC) + (sw >> 1)] = l;
}

// ---------------------------------------------------------------------------
// K1: scores + fused output partial.  Per CTA (64 rows of one batch b):
//   y = A*Wh + (A*2^-12)*(Wres*2^12)   (mma.sync fp16x2, fp32 accum)
//   s = sum_e uw_e*tanh(y+b_e); aun = exp(s)*mask
//   denom: block-reduce aun -> atomicAdd(g_denom[b])
//   out:   thread e accumulates sum_t x[t,e]*aun[t] -> atomicAdd(g_outacc[b,e])
// 2 CTAs/SM: staging tails + epilogue hide under co-resident CTA's MMAs.
// ---------------------------------------------------------------------------
__global__ void __launch_bounds__(THREADS_SC, 2) scores_mma_kernel(
    const float* __restrict__ x, const float* __restrict__ bias,
    const float* __restrict__ uw, const int* __restrict__ mask)
{
    extern __shared__ char smem[];
    const uint32_t sb = smem_u32(smem);
    const int tid  = threadIdx.x;
    const int wid  = tid >> 5;
    const int lane = tid & 31;

    const int mbase = (wid >> 2) * 32;       // warp's row base (2 m-halves)
    const int ncol0 = (wid & 3) * 64;        // warp's col base (4 n-quarters)

    float* red_s  = (float*)(smem + OFF_RED);
    float* uw_s   = (float*)(smem + OFF_UW);
    float* bias_s = (float*)(smem + OFF_BIAS);
    float* aun_s  = (float*)(smem + OFF_AUN);
    for (int i = tid; i < DD; i += THREADS_SC) { uw_s[i] = uw[i]; bias_s[i] = bias[i]; }

    const long long row0 = (long long)blockIdx.x * M_TILE;
    const int b = (int)(row0 >> 11);         // row0 / TT
    const float4* __restrict__ x4 = (const float4*)(x + row0 * DD);

    // x staging: 64 rows x 16 float4; 4 threads/row x 4 float4 each
    const int r_st = tid >> 2;
    const int q_st = (tid & 3) * 4;

    float4 xr[4];

    // prologue: stage chunk 0 (W via cp.async, x via LDG+convert)
    {
        const char* wh = (const char*)g_Whi;
        const char* wl = (const char*)g_Wlo;
#pragma unroll
        for (int j = 0; j < 8; j++) {
            cp16(sb + S_WH + (tid + 256 * j) * 16, wh + (tid + 256 * j) * 16);
            cp16(sb + S_WL + (tid + 256 * j) * 16, wl + (tid + 256 * j) * 16);
        }
        asm volatile("cp.async.commit_group;" ::: "memory");
#pragma unroll
        for (int j = 0; j < 4; j++)
            xr[j] = x4[r_st * (DD / 4) + q_st + j];
#pragma unroll
        for (int j = 0; j < 4; j++) {
            float4 v = xr[j];
            uint32_t swo = SWZ((uint32_t)(r_st * 128 + (q_st + j) * 8));
            *(uint2*)(smem + S_A  + swo) = make_uint2(pkh2(v.x, v.y), pkh2(v.z, v.w));
            *(uint2*)(smem + S_A2 + swo) =
                make_uint2(pkh2(v.x * A2SCALE, v.y * A2SCALE),
                           pkh2(v.z * A2SCALE, v.w * A2SCALE));
        }
        asm volatile("cp.async.wait_group 0;" ::: "memory");
        __syncthreads();
    }

    float acc[2][8][4];
#pragma unroll
    for (int mt = 0; mt < 2; mt++)
#pragma unroll
        for (int j = 0; j < 8; j++)
#pragma unroll
            for (int v = 0; v < 4; v++) acc[mt][j][v] = 0.f;

    // per-lane ldmatrix address components (x4 lane-group layout)
    const int r_a = (lane & 7) + ((lane >> 3) & 1) * 8;   // A: row within m16
    const int k_a = (lane >> 4) * 8;                      // A: k offset
    const int r_b = (lane & 7) + ((lane >> 4) & 1) * 8;   // B: n within pair
    const int k_b = ((lane >> 3) & 1) * 8;                // B: k offset

    for (int kc = 0; kc < NCH; kc++) {
        // prefetch next x chunk into regs during MMAs (STS after)
        if (kc < NCH - 1) {
#pragma unroll
            for (int j = 0; j < 4; j++)
                xr[j] = x4[r_st * (DD / 4) + (kc + 1) * (KC / 4) + q_st + j];
        }

        // --- compute: 4 K16 steps x (2 m16 x 8 n8) x 2 products ---
#pragma unroll
        for (int ks = 0; ks < 4; ks++) {
            const int kk = ks * 16;
            uint32_t ah[2][4], a2[2][4];
#pragma unroll
            for (int mt = 0; mt < 2; mt++) {
                uint32_t ao = SWZ((uint32_t)((mbase + mt * 16 + r_a) * 128 + (kk + k_a) * 2));
                ldsm_x4(ah[mt], sb + S_A  + ao);
                ldsm_x4(a2[mt], sb + S_A2 + ao);
            }
#pragma unroll
            for (int p = 0; p < 4; p++) {
                uint32_t bo = SWZ((uint32_t)((ncol0 + p * 16 + r_b) * 128 + (kk + k_b) * 2));
                uint32_t bh[4], bl[4];
                ldsm_x4(bh, sb + S_WH + bo);
                ldsm_x4(bl, sb + S_WL + bo);
#pragma unroll
                for (int mt = 0; mt < 2; mt++) {
                    mma_16816(acc[mt][2 * p],     ah[mt], bh[0], bh[1]);
                    mma_16816(acc[mt][2 * p + 1], ah[mt], bh[2], bh[3]);
                    mma_16816(acc[mt][2 * p],     a2[mt], bl[0], bl[1]);
                    mma_16816(acc[mt][2 * p + 1], a2[mt], bl[2], bl[3]);
                }
            }
        }

        if (kc < NCH - 1) {
            __syncthreads();   // MMAs done reading stage before overwrite
            // next W chunk via cp.async + convert prefetched x
            const char* wh = (const char*)(g_Whi + (kc + 1) * (DD * KC));
            const char* wl = (const char*)(g_Wlo + (kc + 1) * (DD * KC));
#pragma unroll
            for (int j = 0; j < 8; j++) {
                cp16(sb + S_WH + (tid + 256 * j) * 16, wh + (tid + 256 * j) * 16);
                cp16(sb + S_WL + (tid + 256 * j) * 16, wl + (tid + 256 * j) * 16);
            }
            asm volatile("cp.async.commit_group;" ::: "memory");
#pragma unroll
            for (int j = 0; j < 4; j++) {
                float4 v = xr[j];
                uint32_t swo = SWZ((uint32_t)(r_st * 128 + (q_st + j) * 8));
                *(uint2*)(smem + S_A  + swo) = make_uint2(pkh2(v.x, v.y), pkh2(v.z, v.w));
                *(uint2*)(smem + S_A2 + swo) =
                    make_uint2(pkh2(v.x * A2SCALE, v.y * A2SCALE),
                               pkh2(v.z * A2SCALE, v.w * A2SCALE));
            }
            asm volatile("cp.async.wait_group 0;" ::: "memory");
            __syncthreads();
        }
    }

    // --- epilogue: tanh + uw-dot on fragments ---
    // thread cells: rows mbase+mt*16+(lane>>2)+{0,8}, cols ncol0+j*8+(lane&3)*2+{0,1}
    float part[4] = {0.f, 0.f, 0.f, 0.f};
#pragma unroll
    for (int mt = 0; mt < 2; mt++) {
#pragma unroll
        for (int j = 0; j < 8; j++) {
            const int C = ncol0 + j * 8 + (lane & 3) * 2;
            const float u0 = uw_s[C], u1 = uw_s[C + 1];
            const float b0 = bias_s[C], b1 = bias_s[C + 1];
#pragma unroll
            for (int h = 0; h < 2; h++) {
                float y0 = acc[mt][j][2 * h]     + b0;
                float y1 = acc[mt][j][2 * h + 1] + b1;
                float t0 = 1.f - __fdividef(2.f, __expf(2.f * y0) + 1.f);
                float t1 = 1.f - __fdividef(2.f, __expf(2.f * y1) + 1.f);
                part[mt * 2 + h] += u0 * t0 + u1 * t1;
            }
        }
    }
#pragma unroll
    for (int q = 0; q < 4; q++) {
        part[q] += __shfl_xor_sync(0xFFFFFFFFu, part[q], 1);
        part[q] += __shfl_xor_sync(0xFFFFFFFFu, part[q], 2);
    }
    __syncthreads();   // red_s region free (after MMA loop; reuse)
    if ((lane & 3) == 0) {
        const int rr = lane >> 2;
#pragma unroll
        for (int mt = 0; mt < 2; mt++) {
            red_s[(mbase + mt * 16 + rr) * 4 + (wid & 3)]       = part[mt * 2];
            red_s[(mbase + mt * 16 + rr + 8) * 4 + (wid & 3)]   = part[mt * 2 + 1];
        }
    }
    __syncthreads();

    float aval = 0.f;
    if (tid < M_TILE) {
        float s = red_s[tid * 4] + red_s[tid * 4 + 1] + red_s[tid * 4 + 2] + red_s[tid * 4 + 3];
        long long row = row0 + tid;
        aval = expf(s) * (float)mask[row];
        g_aun[row] = aval;
        aun_s[tid] = aval;
    }
    // block-reduce aval over tid<64 -> atomic add into g_denom[b]
#pragma unroll
    for (int off = 16; off > 0; off >>= 1)
        aval += __shfl_down_sync(0xFFFFFFFFu, aval, off);
    if (tid == 0)  red_s[0] = aval;
    if (tid == 32) red_s[1] = aval;
    __syncthreads();
    if (tid == 0) atomicAdd(&g_denom[b], red_s[0] + red_s[1]);

    // --- fused output partial: thread e sums x[t,e]*aun[t] over 64 rows ---
    {
        const float* __restrict__ xp = x + row0 * DD + tid;   // column tid, stride DD
        float oacc = 0.f;
#pragma unroll 8
        for (int t = 0; t < M_TILE; t++)
            oacc += xp[(size_t)t * DD] * aun_s[t];
        atomicAdd(&g_outacc[b * DD + tid], oacc);
    }
}

// ---------------------------------------------------------------------------
// final: out[b,e] = g_outacc[b,e] / (denom[b]+EPS)
// ---------------------------------------------------------------------------
__global__ void __launch_bounds__(256) final_kernel(float* __restrict__ out)
{
    const int b = blockIdx.x;
    const int e = threadIdx.x;
    out[b * DD + e] = g_outacc[b * DD + e] / (g_denom[b] + 1e-7f);
}

// ---------------------------------------------------------------------------
extern "C" void kernel_launch(void* const* d_in, const int* in_sizes, int n_in,
                              void* d_out, int out_size)
{
    const float* x    = (const float*)d_in[0];
    const float* W    = (const float*)d_in[1];
    const float* bias = (const float*)d_in[2];
    const float* uw   = (const float*)d_in[3];
    const int*   mask = (const int*)d_in[4];
    float* out = (float*)d_out;

    cudaFuncSetAttribute(scores_mma_kernel,
                         cudaFuncAttributeMaxDynamicSharedMemorySize, SMEM_SC);

    pre_kernel<<<(BB * DD) / 256, 256>>>();
    prep_w_kernel<<<DD, 256>>>(W);
    scores_mma_kernel<<<(BB * TT) / M_TILE, THREADS_SC, SMEM_SC>>>(x, bias, uw, mask);
    final_kernel<<<BB, DD>>>(out);
}

// round 17
// speedup vs baseline: 4.2255x; 1.0522x over previous
#include <cuda_runtime.h>
#include <cuda_fp16.h>
#include <math.h>
#include <stdint.h>

// Problem dims (fixed by dataset)
#define BB 64
#define TT 2048
#define DD 256

// scores kernel tiling (mma.sync path: tcgen05 not reachable on compute_103)
#define M_TILE 64         // rows per CTA
#define KC 64             // K chunk (fp16 row = 128B swizzle atom)
#define NCH 4             // DD / KC
#define THREADS_SC 256    // 8 warps: 2 m-halves x 4 n-quarters
#define GRID_SC ((BB * TT) / M_TILE)

// single-stage dynamic smem (~44KB -> 2 CTAs/SM)
#define S_A      0          // 64 x 64 fp16 = 8 KB   (A = fp16(x))
#define S_WH     8192       // 256 x 64 fp16 = 32 KB (Wh = fp16(W))
#define OFF_RED  40960      // 64 rows x 4 n-warp partials fp32 = 1 KB
#define OFF_UW   41984
#define OFF_BIAS 43008
#define OFF_AUN  44032      // 64 fp32
#define SMEM_SC  44544

// ---------------------------------------------------------------------------
// device scratch (allocation-free rule: __device__ globals)
// ---------------------------------------------------------------------------
__device__ float g_denom[BB];               // per-batch sum (EPS added at use)
__device__ float g_outacc[BB * DD];         // unnormalized out accumulators
__device__ unsigned int g_ctr;              // CTA completion counter
__device__ __half g_Whi[NCH * DD * KC];     // W^T fp16, pre-swizzled chunk images

// ---------------------------------------------------------------------------
// helpers
// ---------------------------------------------------------------------------
__device__ __forceinline__ uint32_t smem_u32(const void* p) {
    uint32_t a;
    asm("{ .reg .u64 t; cvta.to.shared.u64 t, %1; cvt.u32.u64 %0, t; }"
        : "=r"(a) : "l"(p));
    return a;
}

#define SWZ(off) ((off) ^ (((off) >> 3) & 0x70))

__device__ __forceinline__ uint32_t pkh2(float a, float b) {
    __half2 h = __floats2half2_rn(a, b);   // .x (low) = a
    return *reinterpret_cast<uint32_t*>(&h);
}

__device__ __forceinline__ void ldsm_x4(uint32_t* q, uint32_t addr) {
    asm volatile("ldmatrix.sync.aligned.m8n8.x4.shared.b16 {%0,%1,%2,%3}, [%4];"
                 : "=r"(q[0]), "=r"(q[1]), "=r"(q[2]), "=r"(q[3]) : "r"(addr));
}

__device__ __forceinline__ void mma_16816(float* d, const uint32_t* a,
                                          uint32_t b0, uint32_t b1) {
    asm volatile(
        "mma.sync.aligned.m16n8k16.row.col.f32.f16.f16.f32 "
        "{%0,%1,%2,%3}, {%4,%5,%6,%7}, {%8,%9}, {%0,%1,%2,%3};"
        : "+f"(d[0]), "+f"(d[1]), "+f"(d[2]), "+f"(d[3])
        : "r"(a[0]), "r"(a[1]), "r"(a[2]), "r"(a[3]), "r"(b0), "r"(b1));
}

__device__ __forceinline__ void cp16(uint32_t saddr, const void* g) {
    asm volatile("cp.async.cg.shared.global [%0], [%1], 16;"
                 :: "r"(saddr), "l"(g) : "memory");
}

// ---------------------------------------------------------------------------
// setup: W^T -> fp16 pre-swizzled chunk images; zero outacc/denom/counter
// ---------------------------------------------------------------------------
__global__ void __launch_bounds__(256) setup_kernel(const float* __restrict__ W)
{
    const int d = blockIdx.x;    // K index 0..255
    const int e = threadIdx.x;   // N index 0..255
    float w = W[d * DD + e];
    const int kc = d >> 6, dl = d & 63;
    uint32_t sw = SWZ((uint32_t)(e * 128 + dl * 2));
    g_Whi[kc * (DD * KC) + (sw >> 1)] = __float2half_rn(w);

    if (d < BB) g_outacc[d * DD + e] = 0.f;
    if (d == BB && e < BB) g_denom[e] = 0.f;
    if (d == BB + 1 && e == 0) g_ctr = 0u;
}

// ---------------------------------------------------------------------------
// K1: scores + fused output.  Per CTA (64 rows of one batch b):
//   y = fp16(x) @ fp16(W)   (mma.sync, fp32 accum)
//   s = sum_e uw_e*tanh(y+b_e); aun = exp(s)*mask
//   denom: block-reduce aun -> atomicAdd(g_denom[b])
//   out:   thread e sums x[t,e]*aun[t] -> atomicAdd(g_outacc[b,e])
//   last CTA (threadfence+counter) divides outacc by denom into d_out.
// ---------------------------------------------------------------------------
__global__ void __launch_bounds__(THREADS_SC, 2) scores_mma_kernel(
    const float* __restrict__ x, const float* __restrict__ bias,
    const float* __restrict__ uw, const int* __restrict__ mask,
    float* __restrict__ out)
{
    extern __shared__ char smem[];
    __shared__ int is_last_s;
    const uint32_t sb = smem_u32(smem);
    const int tid  = threadIdx.x;
    const int wid  = tid >> 5;
    const int lane = tid & 31;

    const int mbase = (wid >> 2) * 32;       // warp's row base (2 m-halves)
    const int ncol0 = (wid & 3) * 64;        // warp's col base (4 n-quarters)

    float* red_s  = (float*)(smem + OFF_RED);
    float* uw_s   = (float*)(smem + OFF_UW);
    float* bias_s = (float*)(smem + OFF_BIAS);
    float* aun_s  = (float*)(smem + OFF_AUN);
    for (int i = tid; i < DD; i += THREADS_SC) { uw_s[i] = uw[i]; bias_s[i] = bias[i]; }

    const long long row0 = (long long)blockIdx.x * M_TILE;
    const int b = (int)(row0 >> 11);         // row0 / TT
    const float4* __restrict__ x4 = (const float4*)(x + row0 * DD);

    // x staging: 64 rows x 16 float4; 4 threads/row x 4 float4 each
    const int r_st = tid >> 2;
    const int q_st = (tid & 3) * 4;

    float4 xr[4];

    // prologue: stage chunk 0 (W via cp.async, x via LDG+convert)
    {
        const char* wh = (const char*)g_Whi;
#pragma unroll
        for (int j = 0; j < 8; j++)
            cp16(sb + S_WH + (tid + 256 * j) * 16, wh + (tid + 256 * j) * 16);
        asm volatile("cp.async.commit_group;" ::: "memory");
#pragma unroll
        for (int j = 0; j < 4; j++)
            xr[j] = x4[r_st * (DD / 4) + q_st + j];
#pragma unroll
        for (int j = 0; j < 4; j++) {
            float4 v = xr[j];
            uint32_t swo = SWZ((uint32_t)(r_st * 128 + (q_st + j) * 8));
            *(uint2*)(smem + S_A + swo) = make_uint2(pkh2(v.x, v.y), pkh2(v.z, v.w));
        }
        asm volatile("cp.async.wait_group 0;" ::: "memory");
        __syncthreads();
    }

    float acc[2][8][4];
#pragma unroll
    for (int mt = 0; mt < 2; mt++)
#pragma unroll
        for (int j = 0; j < 8; j++)
#pragma unroll
            for (int v = 0; v < 4; v++) acc[mt][j][v] = 0.f;

    // per-lane ldmatrix address components (x4 lane-group layout)
    const int r_a = (lane & 7) + ((lane >> 3) & 1) * 8;   // A: row within m16
    const int k_a = (lane >> 4) * 8;                      // A: k offset
    const int r_b = (lane & 7) + ((lane >> 4) & 1) * 8;   // B: n within pair
    const int k_b = ((lane >> 3) & 1) * 8;                // B: k offset

    for (int kc = 0; kc < NCH; kc++) {
        // prefetch next x chunk into regs during MMAs (STS after)
        if (kc < NCH - 1) {
#pragma unroll
            for (int j = 0; j < 4; j++)
                xr[j] = x4[r_st * (DD / 4) + (kc + 1) * (KC / 4) + q_st + j];
        }

        // --- compute: 4 K16 steps x (2 m16 x 8 n8), single fp16 product ---
#pragma unroll
        for (int ks = 0; ks < 4; ks++) {
            const int kk = ks * 16;
            uint32_t ah[2][4];
#pragma unroll
            for (int mt = 0; mt < 2; mt++) {
                uint32_t ao = SWZ((uint32_t)((mbase + mt * 16 + r_a) * 128 + (kk + k_a) * 2));
                ldsm_x4(ah[mt], sb + S_A + ao);
            }
#pragma unroll
            for (int p = 0; p < 4; p++) {
                uint32_t bo = SWZ((uint32_t)((ncol0 + p * 16 + r_b) * 128 + (kk + k_b) * 2));
                uint32_t bh[4];
                ldsm_x4(bh, sb + S_WH + bo);
#pragma unroll
                for (int mt = 0; mt < 2; mt++) {
                    mma_16816(acc[mt][2 * p],     ah[mt], bh[0], bh[1]);
                    mma_16816(acc[mt][2 * p + 1], ah[mt], bh[2], bh[3]);
                }
            }
        }

        if (kc < NCH - 1) {
            __syncthreads();   // MMAs done reading stage before overwrite
            const char* wh = (const char*)(g_Whi + (kc + 1) * (DD * KC));
#pragma unroll
            for (int j = 0; j < 8; j++)
                cp16(sb + S_WH + (tid + 256 * j) * 16, wh + (tid + 256 * j) * 16);
            asm volatile("cp.async.commit_group;" ::: "memory");
#pragma unroll
            for (int j = 0; j < 4; j++) {
                float4 v = xr[j];
                uint32_t swo = SWZ((uint32_t)(r_st * 128 + (q_st + j) * 8));
                *(uint2*)(smem + S_A + swo) = make_uint2(pkh2(v.x, v.y), pkh2(v.z, v.w));
            }
            asm volatile("cp.async.wait_group 0;" ::: "memory");
            __syncthreads();
        }
    }

    // --- epilogue: tanh + uw-dot on fragments ---
    // cells: rows mbase+mt*16+(lane>>2)+{0,8}, cols ncol0+j*8+(lane&3)*2+{0,1}
    float part[4] = {0.f, 0.f, 0.f, 0.f};
#pragma unroll
    for (int mt = 0; mt < 2; mt++) {
#pragma unroll
        for (int j = 0; j < 8; j++) {
            const int C = ncol0 + j * 8 + (lane & 3) * 2;
            const float u0 = uw_s[C], u1 = uw_s[C + 1];
            const float b0 = bias_s[C], b1 = bias_s[C + 1];
#pragma unroll
            for (int h = 0; h < 2; h++) {
                float y0 = acc[mt][j][2 * h]     + b0;
                float y1 = acc[mt][j][2 * h + 1] + b1;
                float t0 = 1.f - __fdividef(2.f, __expf(2.f * y0) + 1.f);
                float t1 = 1.f - __fdividef(2.f, __expf(2.f * y1) + 1.f);
                part[mt * 2 + h] += u0 * t0 + u1 * t1;
            }
        }
    }
#pragma unroll
    for (int q = 0; q < 4; q++) {
        part[q] += __shfl_xor_sync(0xFFFFFFFFu, part[q], 1);
        part[q] += __shfl_xor_sync(0xFFFFFFFFu, part[q], 2);
    }
    __syncthreads();
    if ((lane & 3) == 0) {
        const int rr = lane >> 2;
#pragma unroll
        for (int mt = 0; mt < 2; mt++) {
            red_s[(mbase + mt * 16 + rr) * 4 + (wid & 3)]     = part[mt * 2];
            red_s[(mbase + mt * 16 + rr + 8) * 4 + (wid & 3)] = part[mt * 2 + 1];
        }
    }
    __syncthreads();

    float aval = 0.f;
    if (tid < M_TILE) {
        float s = red_s[tid * 4] + red_s[tid * 4 + 1] + red_s[tid * 4 + 2] + red_s[tid * 4 + 3];
        long long row = row0 + tid;
        aval = expf(s) * (float)mask[row];
        aun_s[tid] = aval;
    }
#pragma unroll
    for (int off = 16; off > 0; off >>= 1)
        aval += __shfl_down_sync(0xFFFFFFFFu, aval, off);
    if (tid == 0)  red_s[0] = aval;
    if (tid == 32) red_s[1] = aval;
    __syncthreads();
    if (tid == 0) atomicAdd(&g_denom[b], red_s[0] + red_s[1]);

    // --- fused output partial: thread e sums x[t,e]*aun[t] over 64 rows ---
    {
        const float* __restrict__ xp = x + row0 * DD + tid;   // column tid, stride DD
        float oacc = 0.f;
#pragma unroll 8
        for (int t = 0; t < M_TILE; t++)
            oacc += xp[(size_t)t * DD] * aun_s[t];
        atomicAdd(&g_outacc[b * DD + tid], oacc);
    }

    // --- completion: last CTA divides by denom and writes d_out ---
    if (tid == 0) {
        __threadfence();
        unsigned int old = atomicAdd(&g_ctr, 1u);
        is_last_s = (old == (unsigned)(GRID_SC - 1));
    }
    __syncthreads();
    if (is_last_s) {
        __threadfence();
#pragma unroll 4
        for (int i = tid; i < BB * DD; i += THREADS_SC) {
            int bb = i >> 8;
            out[i] = g_outacc[i] / (g_denom[bb] + 1e-7f);
        }
    }
}

// ---------------------------------------------------------------------------
extern "C" void kernel_launch(void* const* d_in, const int* in_sizes, int n_in,
                              void* d_out, int out_size)
{
    const float* x    = (const float*)d_in[0];
    const float* W    = (const float*)d_in[1];
    const float* bias = (const float*)d_in[2];
    const float* uw   = (const float*)d_in[3];
    const int*   mask = (const int*)d_in[4];
    float* out = (float*)d_out;

    cudaFuncSetAttribute(scores_mma_kernel,
                         cudaFuncAttributeMaxDynamicSharedMemorySize, SMEM_SC);

    setup_kernel<<<DD, 256>>>(W);
    scores_mma_kernel<<<GRID_SC, THREADS_SC, SMEM_SC>>>(x, bias, uw, mask, out);
}